// round 2
// baseline (speedup 1.0000x reference)
#include <cuda_runtime.h>
#include <math.h>

#define BDIM 2048
#define LSEQ 2048
#define NB   2
#define NH   16
#define NKV  4
#define HDIM 128
#define MROWS (NB*LSEQ)     // 4096
#define KVDIM (NKV*HDIM)    // 512
#define OUT_ELEMS (MROWS*BDIM)   // 8388608 per tuple member

// Scratch (device globals: no allocation allowed in kernel_launch)
__device__ __align__(16) float g_Q[MROWS*BDIM];
__device__ __align__(16) float g_K[MROWS*KVDIM];
__device__ __align__(16) float g_V[MROWS*KVDIM];
__device__ __align__(16) float g_O[MROWS*BDIM];

// ---------------------------------------------------------------------------
// NT SGEMM: C[M,N] = A[M,Kd] * W[N,Kd]^T   (all row-major, ldc = N)
// 128x128 tile, BK=16, 256 threads, 8x8 micro-tile.
// ---------------------------------------------------------------------------
__global__ __launch_bounds__(256) void sgemm_nt(
    const float* __restrict__ A, const float* __restrict__ W,
    float* __restrict__ C, int M, int N, int Kd)
{
    __shared__ float As[16][128];
    __shared__ float Ws[16][128];

    const int tx = threadIdx.x & 15;
    const int ty = threadIdx.x >> 4;
    const int m0 = blockIdx.y << 7;
    const int n0 = blockIdx.x << 7;

    float acc[8][8];
#pragma unroll
    for (int i = 0; i < 8; i++)
#pragma unroll
        for (int j = 0; j < 8; j++) acc[i][j] = 0.f;

    const float* Ab = A + (size_t)m0 * Kd;
    const float* Wb = W + (size_t)n0 * Kd;

    for (int k0 = 0; k0 < Kd; k0 += 16) {
#pragma unroll
        for (int t = 0; t < 2; t++) {
            int id  = threadIdx.x + (t << 8);   // 0..511
            int row = id >> 2;                  // 0..127
            int c4  = (id & 3) << 2;            // 0,4,8,12
            float4 av = *(const float4*)(Ab + (size_t)row * Kd + k0 + c4);
            As[c4 + 0][row] = av.x; As[c4 + 1][row] = av.y;
            As[c4 + 2][row] = av.z; As[c4 + 3][row] = av.w;
            float4 wv = *(const float4*)(Wb + (size_t)row * Kd + k0 + c4);
            Ws[c4 + 0][row] = wv.x; Ws[c4 + 1][row] = wv.y;
            Ws[c4 + 2][row] = wv.z; Ws[c4 + 3][row] = wv.w;
        }
        __syncthreads();
#pragma unroll
        for (int kk = 0; kk < 16; kk++) {
            float a[8], b[8];
            *(float4*)(a)     = *(const float4*)&As[kk][ty * 8];
            *(float4*)(a + 4) = *(const float4*)&As[kk][ty * 8 + 4];
            *(float4*)(b)     = *(const float4*)&Ws[kk][tx * 8];
            *(float4*)(b + 4) = *(const float4*)&Ws[kk][tx * 8 + 4];
#pragma unroll
            for (int i = 0; i < 8; i++)
#pragma unroll
                for (int j = 0; j < 8; j++) acc[i][j] += a[i] * b[j];
        }
        __syncthreads();
    }

#pragma unroll
    for (int i = 0; i < 8; i++) {
        float4 v0 = make_float4(acc[i][0], acc[i][1], acc[i][2], acc[i][3]);
        float4 v1 = make_float4(acc[i][4], acc[i][5], acc[i][6], acc[i][7]);
        size_t base = (size_t)(m0 + ty * 8 + i) * N + n0 + tx * 8;
        *(float4*)&C[base]     = v0;
        *(float4*)&C[base + 4] = v1;
    }
}

// ---------------------------------------------------------------------------
// RoPE on Q (in place). One thread per (row, head, dim-pair).
// ---------------------------------------------------------------------------
__global__ void rope_q_kernel(const float* __restrict__ fc, const float* __restrict__ fs)
{
    int idx = blockIdx.x * blockDim.x + threadIdx.x;   // < MROWS*1024
    int bl = idx >> 10;
    int p  = idx & 1023;
    int h  = p >> 6;
    int dp = p & 63;
    int l  = bl & (LSEQ - 1);
    float c = fc[l * 64 + dp];
    float s = fs[l * 64 + dp];
    float2* q = (float2*)&g_Q[(size_t)bl * BDIM + h * HDIM + dp * 2];
    float2 v = *q;
    float2 r;
    r.x = v.x * c - v.y * s;
    r.y = v.x * s + v.y * c;
    *q = r;
}

// ---------------------------------------------------------------------------
// RoPE on K (in place) + write keys output (4-way head replication,
// layout [B, NH, L, HD]).
// ---------------------------------------------------------------------------
__global__ void rope_k_keys_kernel(const float* __restrict__ fc, const float* __restrict__ fs,
                                   float* __restrict__ keys)
{
    int idx = blockIdx.x * blockDim.x + threadIdx.x;   // < MROWS*256
    int bl  = idx >> 8;
    int p   = idx & 255;
    int kvh = p >> 6;
    int dp  = p & 63;
    int b   = bl >> 11;            // /LSEQ
    int l   = bl & (LSEQ - 1);
    float c = fc[l * 64 + dp];
    float s = fs[l * 64 + dp];
    float2* kp = (float2*)&g_K[(size_t)bl * KVDIM + kvh * HDIM + dp * 2];
    float2 v = *kp;
    float2 r;
    r.x = v.x * c - v.y * s;
    r.y = v.x * s + v.y * c;
    *kp = r;
#pragma unroll
    for (int rep = 0; rep < 4; rep++) {
        int h = kvh * 4 + rep;
        *(float2*)&keys[(((size_t)(b * NH + h)) * LSEQ + l) * HDIM + dp * 2] = r;
    }
}

// ---------------------------------------------------------------------------
// values output: replicate V 4x into [B, NH, L, HD]. One thread per float4 of
// the compact V.
// ---------------------------------------------------------------------------
__global__ void values_copy_kernel(float* __restrict__ values)
{
    int idx = blockIdx.x * blockDim.x + threadIdx.x;   // < MROWS*128
    int bl  = idx >> 7;
    int p   = idx & 127;           // float4 index within 512 floats
    int kvh = p >> 5;
    int c4  = p & 31;
    int b   = bl >> 11;
    int l   = bl & (LSEQ - 1);
    float4 v = *(const float4*)&g_V[(size_t)bl * KVDIM + p * 4];
#pragma unroll
    for (int rep = 0; rep < 4; rep++) {
        int h = kvh * 4 + rep;
        *(float4*)&values[(((size_t)(b * NH + h)) * LSEQ + l) * HDIM + c4 * 4] = v;
    }
}

// ---------------------------------------------------------------------------
// Flash attention (fp32, causal, GQA). BR=BC=64, HD=128, 256 threads.
// smem: Qs[64][128], KT[128][64] (reused as Vs[64][128]), Ss[64][64],
// row stats. Writes attention output into g_O in [B, L, H*HD] layout.
// ---------------------------------------------------------------------------
#define BR 64
#define BC 64
#define ATTN_SMEM ((8192 + 8192 + 4096 + 192) * 4)

__global__ __launch_bounds__(256, 2) void flash_attn_kernel()
{
    extern __shared__ float sm[];
    float* Qs     = sm;              // [64][128]
    float* KT     = sm + 8192;       // [128][64]  (K^T) / reused as Vs[64][128]
    float* Ss     = sm + 16384;      // [64][64]
    float* row_m  = sm + 20480;
    float* row_l  = row_m + 64;
    float* row_al = row_l + 64;

    const int tid = threadIdx.x;
    const int qt  = blockIdx.x;
    const int bh  = blockIdx.y;
    const int b   = bh >> 4;
    const int h   = bh & 15;
    const int kv  = h >> 2;
    const int q0  = qt * BR;

    const size_t qbase = ((size_t)(b * LSEQ + q0)) * BDIM + h * HDIM;
    const size_t kbase = ((size_t)(b * LSEQ)) * KVDIM + kv * HDIM;

    // Load Q tile (64x128)
#pragma unroll
    for (int t = 0; t < 8; t++) {
        int id = tid + t * 256;
        int r  = id >> 5, c4 = id & 31;
        *(float4*)&Qs[r * 128 + c4 * 4] =
            *(const float4*)&g_Q[qbase + (size_t)r * BDIM + c4 * 4];
    }
    if (tid < 64) { row_m[tid] = -1e30f; row_l[tid] = 0.f; }

    const int ty = tid >> 4;       // S rows group / PV row group (4 rows)
    const int tx = tid & 15;       // S cols group / PV col chunk (8 cols)
    const int sr = tid >> 2;       // softmax row
    const int sq = tid & 3;        // softmax quarter (16 cols each)

    float o[4][8];
#pragma unroll
    for (int i = 0; i < 4; i++)
#pragma unroll
        for (int j = 0; j < 8; j++) o[i][j] = 0.f;

    const float scale = 0.08838834764831845f;  // 1/sqrt(128)
    const int ntiles = qt + 1;

    for (int jt = 0; jt < ntiles; jt++) {
        __syncthreads();   // protect KT/Vs + Ss from previous iteration

        // Load K^T: KT[d][c] = K[j*64+c][d]
#pragma unroll
        for (int t = 0; t < 8; t++) {
            int id = tid + t * 256;
            int c  = id & 63;
            int d4 = id >> 6;    // 0..31
            float4 kvec = *(const float4*)&g_K[kbase + (size_t)(jt * BC + c) * KVDIM + d4 * 4];
            KT[(d4 * 4 + 0) * 64 + c] = kvec.x;
            KT[(d4 * 4 + 1) * 64 + c] = kvec.y;
            KT[(d4 * 4 + 2) * 64 + c] = kvec.z;
            KT[(d4 * 4 + 3) * 64 + c] = kvec.w;
        }
        __syncthreads();

        // S = scale * Q K^T   (4x4 per thread)
        float accS[4][4];
#pragma unroll
        for (int i = 0; i < 4; i++)
#pragma unroll
            for (int j = 0; j < 4; j++) accS[i][j] = 0.f;

#pragma unroll 4
        for (int d = 0; d < 128; d += 4) {
            float4 aF[4], bF[4];
#pragma unroll
            for (int i = 0; i < 4; i++)
                aF[i] = *(const float4*)&Qs[(ty * 4 + i) * 128 + d];
#pragma unroll
            for (int dd = 0; dd < 4; dd++)
                bF[dd] = *(const float4*)&KT[(d + dd) * 64 + tx * 4];
#pragma unroll
            for (int i = 0; i < 4; i++) {
                const float* ap = (const float*)&aF[i];
#pragma unroll
                for (int dd = 0; dd < 4; dd++) {
                    const float av = ap[dd];
                    const float* bp = (const float*)&bF[dd];
#pragma unroll
                    for (int jj = 0; jj < 4; jj++)
                        accS[i][jj] += av * bp[jj];
                }
            }
        }

        // mask (diag tile only) + scale + store to Ss
        const bool diag = (jt == qt);
#pragma unroll
        for (int i = 0; i < 4; i++) {
            int r = ty * 4 + i;
            float4 v;
            v.x = accS[i][0] * scale;
            v.y = accS[i][1] * scale;
            v.z = accS[i][2] * scale;
            v.w = accS[i][3] * scale;
            if (diag) {
                if (tx * 4 + 0 > r) v.x = -1e30f;
                if (tx * 4 + 1 > r) v.y = -1e30f;
                if (tx * 4 + 2 > r) v.z = -1e30f;
                if (tx * 4 + 3 > r) v.w = -1e30f;
            }
            *(float4*)&Ss[r * 64 + tx * 4] = v;
        }
        __syncthreads();

        // online softmax (4 threads per row) — then V load (reuses KT buffer)
        {
            float4 sv[4];
            float pmax = -1e30f;
#pragma unroll
            for (int t = 0; t < 4; t++) {
                sv[t] = *(const float4*)&Ss[sr * 64 + sq * 16 + t * 4];
                pmax = fmaxf(pmax, fmaxf(fmaxf(sv[t].x, sv[t].y), fmaxf(sv[t].z, sv[t].w)));
            }
            pmax = fmaxf(pmax, __shfl_xor_sync(0xffffffffu, pmax, 1));
            pmax = fmaxf(pmax, __shfl_xor_sync(0xffffffffu, pmax, 2));
            float mold = row_m[sr];
            float mnew = fmaxf(mold, pmax);
            float alpha = __expf(mold - mnew);
            float lsum = 0.f;
#pragma unroll
            for (int t = 0; t < 4; t++) {
                sv[t].x = __expf(sv[t].x - mnew);
                sv[t].y = __expf(sv[t].y - mnew);
                sv[t].z = __expf(sv[t].z - mnew);
                sv[t].w = __expf(sv[t].w - mnew);
                lsum += sv[t].x + sv[t].y + sv[t].z + sv[t].w;
                *(float4*)&Ss[sr * 64 + sq * 16 + t * 4] = sv[t];
            }
            lsum += __shfl_xor_sync(0xffffffffu, lsum, 1);
            lsum += __shfl_xor_sync(0xffffffffu, lsum, 2);
            if (sq == 0) {
                row_l[sr]  = row_l[sr] * alpha + lsum;
                row_m[sr]  = mnew;
                row_al[sr] = alpha;
            }
        }

        // Load V tile (row-major) into the KT buffer
        float* Vs = KT;
#pragma unroll
        for (int t = 0; t < 8; t++) {
            int id = tid + t * 256;
            int r  = id >> 5, c4 = id & 31;
            *(float4*)&Vs[r * 128 + c4 * 4] =
                *(const float4*)&g_V[kbase + (size_t)(jt * BC + r) * KVDIM + c4 * 4];
        }
        __syncthreads();

        // rescale O, then O += P V  (4 rows x 8 cols per thread)
        float al[4];
#pragma unroll
        for (int i = 0; i < 4; i++) al[i] = row_al[ty * 4 + i];
#pragma unroll
        for (int i = 0; i < 4; i++)
#pragma unroll
            for (int j = 0; j < 8; j++) o[i][j] *= al[i];

#pragma unroll 2
        for (int k = 0; k < 64; k++) {
            float p0 = Ss[(ty * 4 + 0) * 64 + k];
            float p1 = Ss[(ty * 4 + 1) * 64 + k];
            float p2 = Ss[(ty * 4 + 2) * 64 + k];
            float p3 = Ss[(ty * 4 + 3) * 64 + k];
            float4 v0 = *(const float4*)&Vs[k * 128 + tx * 8];
            float4 v1 = *(const float4*)&Vs[k * 128 + tx * 8 + 4];
            const float* vp0 = (const float*)&v0;
            const float* vp1 = (const float*)&v1;
#pragma unroll
            for (int j = 0; j < 4; j++) {
                o[0][j]     += p0 * vp0[j];
                o[1][j]     += p1 * vp0[j];
                o[2][j]     += p2 * vp0[j];
                o[3][j]     += p3 * vp0[j];
                o[0][j + 4] += p0 * vp1[j];
                o[1][j + 4] += p1 * vp1[j];
                o[2][j + 4] += p2 * vp1[j];
                o[3][j + 4] += p3 * vp1[j];
            }
        }
    }

    // final normalize + store into g_O ([B, L, H*HD] layout)
    const size_t obase = ((size_t)(b * LSEQ + q0)) * BDIM + h * HDIM;
#pragma unroll
    for (int i = 0; i < 4; i++) {
        int r = ty * 4 + i;
        float linv = 1.f / row_l[r];
        float4 v0 = make_float4(o[i][0] * linv, o[i][1] * linv, o[i][2] * linv, o[i][3] * linv);
        float4 v1 = make_float4(o[i][4] * linv, o[i][5] * linv, o[i][6] * linv, o[i][7] * linv);
        *(float4*)&g_O[obase + (size_t)r * BDIM + tx * 8]     = v0;
        *(float4*)&g_O[obase + (size_t)r * BDIM + tx * 8 + 4] = v1;
    }
}

// ---------------------------------------------------------------------------
extern "C" void kernel_launch(void* const* d_in, const int* in_sizes, int n_in,
                              void* d_out, int out_size)
{
    const float* x  = (const float*)d_in[0];
    const float* fc = (const float*)d_in[1];
    const float* fs = (const float*)d_in[2];
    const float* wq = (const float*)d_in[3];
    const float* wk = (const float*)d_in[4];
    const float* wv = (const float*)d_in[5];
    const float* wo = (const float*)d_in[6];

    float* out    = (float*)d_out;
    float* keys   = out + OUT_ELEMS;
    float* values = keys + OUT_ELEMS;

    float *qptr, *kptr, *vptr, *optr;
    cudaGetSymbolAddress((void**)&qptr, g_Q);
    cudaGetSymbolAddress((void**)&kptr, g_K);
    cudaGetSymbolAddress((void**)&vptr, g_V);
    cudaGetSymbolAddress((void**)&optr, g_O);

    // No static guard (harness rule): set the attribute on every call.
    // Non-stream API, safe under graph capture, deterministic.
    cudaFuncSetAttribute(flash_attn_kernel,
                         cudaFuncAttributeMaxDynamicSharedMemorySize, ATTN_SMEM);

    dim3 blk(256);
    dim3 gq(BDIM / 128, MROWS / 128);   // (16, 32)
    dim3 gkv(KVDIM / 128, MROWS / 128); // (4, 32)

    sgemm_nt<<<gq,  blk>>>(x, wq, qptr, MROWS, BDIM,  BDIM);
    sgemm_nt<<<gkv, blk>>>(x, wk, kptr, MROWS, KVDIM, BDIM);
    sgemm_nt<<<gkv, blk>>>(x, wv, vptr, MROWS, KVDIM, BDIM);

    rope_q_kernel<<<MROWS * 1024 / 256, blk>>>(fc, fs);
    rope_k_keys_kernel<<<MROWS * 256 / 256, blk>>>(fc, fs, keys);
    values_copy_kernel<<<MROWS * 128 / 256, blk>>>(values);

    dim3 ga(LSEQ / BR, NB * NH);        // (32, 32)
    flash_attn_kernel<<<ga, blk, ATTN_SMEM>>>();

    sgemm_nt<<<gq, blk>>>(optr, wo, out, MROWS, BDIM, BDIM);
}

// round 3
// speedup vs baseline: 3.0223x; 3.0223x over previous
#include <cuda_runtime.h>
#include <math.h>
#include <stdint.h>

#define BDIM 2048
#define LSEQ 2048
#define NB   2
#define NH   16
#define NKV  4
#define HDIM 128
#define MROWS (NB*LSEQ)     // 4096
#define KVDIM (NKV*HDIM)    // 512
#define OUT_ELEMS (MROWS*BDIM)

// Scratch (device globals: no allocation allowed in kernel_launch)
__device__ __align__(16) float g_Q[MROWS*BDIM];
__device__ __align__(16) float g_K[MROWS*KVDIM];
__device__ __align__(16) float g_V[MROWS*KVDIM];
__device__ __align__(16) float g_O[MROWS*BDIM];

// ---------------------------------------------------------------------------
// helpers
// ---------------------------------------------------------------------------
__device__ __forceinline__ float to_tf32(float x) {
    uint32_t u;
    asm("cvt.rna.tf32.f32 %0, %1;" : "=r"(u) : "f"(x));
    return __uint_as_float(u);
}
__device__ __forceinline__ uint32_t fu(float x) { return __float_as_uint(x); }

#define MMA_TF32(d, a0, a1, a2, a3, b0, b1)                                   \
    asm volatile("mma.sync.aligned.m16n8k8.row.col.f32.tf32.tf32.f32 "        \
                 "{%0,%1,%2,%3}, {%4,%5,%6,%7}, {%8,%9}, {%0,%1,%2,%3};"      \
                 : "+f"(d[0]), "+f"(d[1]), "+f"(d[2]), "+f"(d[3])             \
                 : "r"(a0), "r"(a1), "r"(a2), "r"(a3), "r"(b0), "r"(b1))

// ---------------------------------------------------------------------------
// NT GEMM via tf32 mma: C[M,N] = A[M,Kd] * W[N,Kd]^T (row-major, ldc=N)
// 128x128 tile, BK=32, 256 threads (8 warps, 64x32 warp tile), double buffer.
// ---------------------------------------------------------------------------
#define PADK 36
#define TILEF (128 * PADK)
#define GEMM_SMEM (2 * 2 * TILEF * 4)   // 73728 B

__global__ __launch_bounds__(256) void mma_gemm_nt(
    const float* __restrict__ A, const float* __restrict__ W,
    float* __restrict__ C, int M, int N, int Kd)
{
    extern __shared__ float sh[];
    const int tid  = threadIdx.x;
    const int lane = tid & 31;
    const int wid  = tid >> 5;
    const int g    = lane >> 2;
    const int t    = lane & 3;
    const int wm   = wid & 1;      // 0..1 -> 64-row block
    const int wn   = wid >> 1;     // 0..3 -> 32-col block
    const int m0   = blockIdx.y << 7;
    const int n0   = blockIdx.x << 7;

    const int lrow = tid >> 3;         // 0..31
    const int lcol = (tid & 7) << 2;   // 0,4,...,28

    float acc[4][4][4];
#pragma unroll
    for (int i = 0; i < 4; i++)
#pragma unroll
        for (int j = 0; j < 4; j++)
#pragma unroll
            for (int r = 0; r < 4; r++) acc[i][j][r] = 0.f;

    const float* Ag = A + (size_t)(m0 + lrow) * Kd + lcol;
    const float* Wg = W + (size_t)(n0 + lrow) * Kd + lcol;

    float4 ra[4], rw[4];
    // prefetch tile 0
#pragma unroll
    for (int i = 0; i < 4; i++) {
        ra[i] = *(const float4*)(Ag + (size_t)(i * 32) * Kd);
        rw[i] = *(const float4*)(Wg + (size_t)(i * 32) * Kd);
    }

    int p = 0;
    {   // store tile 0
        float* As = sh;               // buffer 0
        float* Ws = sh + TILEF;
#pragma unroll
        for (int i = 0; i < 4; i++) {
            float4 a = ra[i], w = rw[i];
            a.x = to_tf32(a.x); a.y = to_tf32(a.y); a.z = to_tf32(a.z); a.w = to_tf32(a.w);
            w.x = to_tf32(w.x); w.y = to_tf32(w.y); w.z = to_tf32(w.z); w.w = to_tf32(w.w);
            *(float4*)&As[(lrow + i * 32) * PADK + lcol] = a;
            *(float4*)&Ws[(lrow + i * 32) * PADK + lcol] = w;
        }
    }
    __syncthreads();

    for (int k0 = 32; k0 <= Kd; k0 += 32) {
        const bool more = (k0 < Kd);
        if (more) {
#pragma unroll
            for (int i = 0; i < 4; i++) {
                ra[i] = *(const float4*)(Ag + (size_t)(i * 32) * Kd + k0);
                rw[i] = *(const float4*)(Wg + (size_t)(i * 32) * Kd + k0);
            }
        }
        // compute on buffer p
        {
            const float* As = sh + p * (2 * TILEF);
            const float* Ws = As + TILEF;
#pragma unroll
            for (int kk = 0; kk < 32; kk += 8) {
                uint32_t af[4][4], bf[4][2];
#pragma unroll
                for (int i = 0; i < 4; i++) {
                    int base = (wm * 64 + i * 16 + g) * PADK + kk + t;
                    af[i][0] = fu(As[base]);
                    af[i][1] = fu(As[base + 8 * PADK]);
                    af[i][2] = fu(As[base + 4]);
                    af[i][3] = fu(As[base + 8 * PADK + 4]);
                }
#pragma unroll
                for (int j = 0; j < 4; j++) {
                    int base = (wn * 32 + j * 8 + g) * PADK + kk + t;
                    bf[j][0] = fu(Ws[base]);
                    bf[j][1] = fu(Ws[base + 4]);
                }
#pragma unroll
                for (int i = 0; i < 4; i++)
#pragma unroll
                    for (int j = 0; j < 4; j++)
                        MMA_TF32(acc[i][j], af[i][0], af[i][1], af[i][2], af[i][3],
                                 bf[j][0], bf[j][1]);
            }
        }
        if (more) {
            float* As = sh + (1 - p) * (2 * TILEF);
            float* Ws = As + TILEF;
#pragma unroll
            for (int i = 0; i < 4; i++) {
                float4 a = ra[i], w = rw[i];
                a.x = to_tf32(a.x); a.y = to_tf32(a.y); a.z = to_tf32(a.z); a.w = to_tf32(a.w);
                w.x = to_tf32(w.x); w.y = to_tf32(w.y); w.z = to_tf32(w.z); w.w = to_tf32(w.w);
                *(float4*)&As[(lrow + i * 32) * PADK + lcol] = a;
                *(float4*)&Ws[(lrow + i * 32) * PADK + lcol] = w;
            }
            __syncthreads();
            p ^= 1;
        }
    }

    // epilogue
#pragma unroll
    for (int i = 0; i < 4; i++) {
        int row = m0 + wm * 64 + i * 16 + g;
#pragma unroll
        for (int j = 0; j < 4; j++) {
            int col = n0 + wn * 32 + j * 8 + 2 * t;
            *(float2*)&C[(size_t)row * N + col] = make_float2(acc[i][j][0], acc[i][j][1]);
            *(float2*)&C[(size_t)(row + 8) * N + col] = make_float2(acc[i][j][2], acc[i][j][3]);
        }
    }
}

// ---------------------------------------------------------------------------
// RoPE on Q (in place).
// ---------------------------------------------------------------------------
__global__ void rope_q_kernel(const float* __restrict__ fc, const float* __restrict__ fs)
{
    int idx = blockIdx.x * blockDim.x + threadIdx.x;
    int bl = idx >> 10;
    int p  = idx & 1023;
    int h  = p >> 6;
    int dp = p & 63;
    int l  = bl & (LSEQ - 1);
    float c = fc[l * 64 + dp];
    float s = fs[l * 64 + dp];
    float2* q = (float2*)&g_Q[(size_t)bl * BDIM + h * HDIM + dp * 2];
    float2 v = *q;
    float2 r;
    r.x = v.x * c - v.y * s;
    r.y = v.x * s + v.y * c;
    *q = r;
}

// ---------------------------------------------------------------------------
// RoPE on K (in place) + keys output [B, NH, L, HD] (4-way replication)
// ---------------------------------------------------------------------------
__global__ void rope_k_keys_kernel(const float* __restrict__ fc, const float* __restrict__ fs,
                                   float* __restrict__ keys)
{
    int idx = blockIdx.x * blockDim.x + threadIdx.x;
    int bl  = idx >> 8;
    int p   = idx & 255;
    int kvh = p >> 6;
    int dp  = p & 63;
    int b   = bl >> 11;
    int l   = bl & (LSEQ - 1);
    float c = fc[l * 64 + dp];
    float s = fs[l * 64 + dp];
    float2* kp = (float2*)&g_K[(size_t)bl * KVDIM + kvh * HDIM + dp * 2];
    float2 v = *kp;
    float2 r;
    r.x = v.x * c - v.y * s;
    r.y = v.x * s + v.y * c;
    *kp = r;
#pragma unroll
    for (int rep = 0; rep < 4; rep++) {
        int h = kvh * 4 + rep;
        *(float2*)&keys[(((size_t)(b * NH + h)) * LSEQ + l) * HDIM + dp * 2] = r;
    }
}

// ---------------------------------------------------------------------------
// values output: replicate V 4x into [B, NH, L, HD]
// ---------------------------------------------------------------------------
__global__ void values_copy_kernel(float* __restrict__ values)
{
    int idx = blockIdx.x * blockDim.x + threadIdx.x;
    int bl  = idx >> 7;
    int p   = idx & 127;
    int kvh = p >> 5;
    int c4  = p & 31;
    int b   = bl >> 11;
    int l   = bl & (LSEQ - 1);
    float4 v = *(const float4*)&g_V[(size_t)bl * KVDIM + p * 4];
#pragma unroll
    for (int rep = 0; rep < 4; rep++) {
        int h = kvh * 4 + rep;
        *(float4*)&values[(((size_t)(b * NH + h)) * LSEQ + l) * HDIM + c4 * 4] = v;
    }
}

// ---------------------------------------------------------------------------
// Flash attention with tf32 mma. BR=BC=64, HD=128, 256 threads (8 warps).
// Warp layout: wm = wid&3 (16-row block), wn = wid>>2 (half of cols).
// smem: Qs[64][132], Ks[64][132] (reused for V), Ss[64][76], stats.
// ---------------------------------------------------------------------------
#define PADQ 132
#define PADS 76
#define ATTN_FLOATS (64 * PADQ + 64 * PADQ + 64 * PADS + 192)
#define ATTN_SMEM (ATTN_FLOATS * 4)

__global__ __launch_bounds__(256) void flash_attn_mma()
{
    extern __shared__ float sm[];
    float* Qs     = sm;                       // [64][132]
    float* Ks     = Qs + 64 * PADQ;           // [64][132] (K then V)
    float* Ss     = Ks + 64 * PADQ;           // [64][76]
    float* row_m  = Ss + 64 * PADS;
    float* row_l  = row_m + 64;
    float* row_al = row_l + 64;

    const int tid  = threadIdx.x;
    const int lane = tid & 31;
    const int wid  = tid >> 5;
    const int g    = lane >> 2;
    const int t    = lane & 3;
    const int wm   = wid & 3;       // 16-row block
    const int wn   = wid >> 2;      // 0..1

    const int qt = blockIdx.x;
    const int bh = blockIdx.y;
    const int b  = bh >> 4;
    const int h  = bh & 15;
    const int kv = h >> 2;
    const int q0 = qt * 64;

    const size_t qbase = ((size_t)(b * LSEQ + q0)) * BDIM + h * HDIM;
    const size_t kbase = ((size_t)(b * LSEQ)) * KVDIM + kv * HDIM;

    // Load Q tile (64x128) -> tf32-rounded smem
#pragma unroll
    for (int pp = 0; pp < 8; pp++) {
        int id = tid + pp * 256;
        int r  = id >> 5, c4 = (id & 31) << 2;
        float4 v = *(const float4*)&g_Q[qbase + (size_t)r * BDIM + c4];
        v.x = to_tf32(v.x); v.y = to_tf32(v.y); v.z = to_tf32(v.z); v.w = to_tf32(v.w);
        *(float4*)&Qs[r * PADQ + c4] = v;
    }
    if (tid < 64) { row_m[tid] = -1e30f; row_l[tid] = 0.f; }

    const int sr = tid >> 2;   // softmax row
    const int sq = tid & 3;    // softmax quarter

    // O accumulators: 1 m-tile x 8 n-tiles per warp (rows wm*16+g, +8; cols wn*64+j*8+2t)
    float o[8][4];
#pragma unroll
    for (int j = 0; j < 8; j++)
#pragma unroll
        for (int r = 0; r < 4; r++) o[j][r] = 0.f;

    const float scale = 0.08838834764831845f;  // 1/sqrt(128)
    const int ntiles = qt + 1;

    for (int jt = 0; jt < ntiles; jt++) {
        __syncthreads();   // prev PV reads of Ss/Ks done

        // Load K tile (64x128) -> tf32 smem
#pragma unroll
        for (int pp = 0; pp < 8; pp++) {
            int id = tid + pp * 256;
            int r  = id >> 5, c4 = (id & 31) << 2;
            float4 v = *(const float4*)&g_K[kbase + (size_t)(jt * 64 + r) * KVDIM + c4];
            v.x = to_tf32(v.x); v.y = to_tf32(v.y); v.z = to_tf32(v.z); v.w = to_tf32(v.w);
            *(float4*)&Ks[r * PADQ + c4] = v;
        }
        __syncthreads();

        // S = Q K^T : per warp 1 m16 x 4 n8 tiles, k=128
        float sacc[4][4];
#pragma unroll
        for (int j = 0; j < 4; j++)
#pragma unroll
            for (int r = 0; r < 4; r++) sacc[j][r] = 0.f;

#pragma unroll
        for (int kk = 0; kk < 128; kk += 8) {
            int abase = (wm * 16 + g) * PADQ + kk + t;
            uint32_t a0 = fu(Qs[abase]);
            uint32_t a1 = fu(Qs[abase + 8 * PADQ]);
            uint32_t a2 = fu(Qs[abase + 4]);
            uint32_t a3 = fu(Qs[abase + 8 * PADQ + 4]);
            uint32_t bf[4][2];
#pragma unroll
            for (int j = 0; j < 4; j++) {
                int bb = (wn * 32 + j * 8 + g) * PADQ + kk + t;
                bf[j][0] = fu(Ks[bb]);
                bf[j][1] = fu(Ks[bb + 4]);
            }
#pragma unroll
            for (int j = 0; j < 4; j++)
                MMA_TF32(sacc[j], a0, a1, a2, a3, bf[j][0], bf[j][1]);
        }

        // scale + causal mask (diag tile) + store S to Ss
        const bool diag = (jt == qt);
#pragma unroll
        for (int j = 0; j < 4; j++) {
            int r0 = wm * 16 + g;
            int c0 = wn * 32 + j * 8 + 2 * t;
            float s0 = sacc[j][0] * scale;
            float s1 = sacc[j][1] * scale;
            float s2 = sacc[j][2] * scale;
            float s3 = sacc[j][3] * scale;
            if (diag) {
                if (c0     > r0)     s0 = -1e30f;
                if (c0 + 1 > r0)     s1 = -1e30f;
                if (c0     > r0 + 8) s2 = -1e30f;
                if (c0 + 1 > r0 + 8) s3 = -1e30f;
            }
            *(float2*)&Ss[r0 * PADS + c0]       = make_float2(s0, s1);
            *(float2*)&Ss[(r0 + 8) * PADS + c0] = make_float2(s2, s3);
        }
        __syncthreads();

        // online softmax (4 threads per row); P written back tf32-rounded.
        {
            float4 sv[4];
            float pmax = -1e30f;
#pragma unroll
            for (int tt = 0; tt < 4; tt++) {
                sv[tt] = *(const float4*)&Ss[sr * PADS + sq * 16 + tt * 4];
                pmax = fmaxf(pmax, fmaxf(fmaxf(sv[tt].x, sv[tt].y), fmaxf(sv[tt].z, sv[tt].w)));
            }
            pmax = fmaxf(pmax, __shfl_xor_sync(0xffffffffu, pmax, 1));
            pmax = fmaxf(pmax, __shfl_xor_sync(0xffffffffu, pmax, 2));
            float mold = row_m[sr];
            float mnew = fmaxf(mold, pmax);
            float alpha = __expf(mold - mnew);
            float lsum = 0.f;
#pragma unroll
            for (int tt = 0; tt < 4; tt++) {
                sv[tt].x = __expf(sv[tt].x - mnew);
                sv[tt].y = __expf(sv[tt].y - mnew);
                sv[tt].z = __expf(sv[tt].z - mnew);
                sv[tt].w = __expf(sv[tt].w - mnew);
                lsum += sv[tt].x + sv[tt].y + sv[tt].z + sv[tt].w;
                sv[tt].x = to_tf32(sv[tt].x);
                sv[tt].y = to_tf32(sv[tt].y);
                sv[tt].z = to_tf32(sv[tt].z);
                sv[tt].w = to_tf32(sv[tt].w);
                *(float4*)&Ss[sr * PADS + sq * 16 + tt * 4] = sv[tt];
            }
            lsum += __shfl_xor_sync(0xffffffffu, lsum, 1);
            lsum += __shfl_xor_sync(0xffffffffu, lsum, 2);
            if (sq == 0) {
                row_l[sr]  = row_l[sr] * alpha + lsum;
                row_m[sr]  = mnew;
                row_al[sr] = alpha;
            }
        }

        // Load V tile into Ks buffer (tf32)
#pragma unroll
        for (int pp = 0; pp < 8; pp++) {
            int id = tid + pp * 256;
            int r  = id >> 5, c4 = (id & 31) << 2;
            float4 v = *(const float4*)&g_V[kbase + (size_t)(jt * 64 + r) * KVDIM + c4];
            v.x = to_tf32(v.x); v.y = to_tf32(v.y); v.z = to_tf32(v.z); v.w = to_tf32(v.w);
            *(float4*)&Ks[r * PADQ + c4] = v;
        }
        __syncthreads();

        // rescale O by alpha
        float al0 = row_al[wm * 16 + g];
        float al1 = row_al[wm * 16 + g + 8];
#pragma unroll
        for (int j = 0; j < 8; j++) {
            o[j][0] *= al0; o[j][1] *= al0;
            o[j][2] *= al1; o[j][3] *= al1;
        }

        // O += P V : per warp 1 m16 x 8 n8 tiles, k=64. B = V[k][n] directly.
#pragma unroll
        for (int kk = 0; kk < 64; kk += 8) {
            int abase = (wm * 16 + g) * PADS + kk + t;
            uint32_t a0 = fu(Ss[abase]);
            uint32_t a1 = fu(Ss[abase + 8 * PADS]);
            uint32_t a2 = fu(Ss[abase + 4]);
            uint32_t a3 = fu(Ss[abase + 8 * PADS + 4]);
#pragma unroll
            for (int j = 0; j < 8; j++) {
                int bb = (kk + t) * PADQ + wn * 64 + j * 8 + g;
                uint32_t b0 = fu(Ks[bb]);
                uint32_t b1 = fu(Ks[bb + 4 * PADQ]);
                MMA_TF32(o[j], a0, a1, a2, a3, b0, b1);
            }
        }
    }

    // final normalize + store O ([B, L, H*HD] layout)
    const size_t obase = ((size_t)(b * LSEQ + q0)) * BDIM + h * HDIM;
    float linv0 = 1.f / row_l[wm * 16 + g];
    float linv1 = 1.f / row_l[wm * 16 + g + 8];
    int r0 = wm * 16 + g;
#pragma unroll
    for (int j = 0; j < 8; j++) {
        int col = wn * 64 + j * 8 + 2 * t;
        *(float2*)&g_O[obase + (size_t)r0 * BDIM + col] =
            make_float2(o[j][0] * linv0, o[j][1] * linv0);
        *(float2*)&g_O[obase + (size_t)(r0 + 8) * BDIM + col] =
            make_float2(o[j][2] * linv1, o[j][3] * linv1);
    }
}

// ---------------------------------------------------------------------------
extern "C" void kernel_launch(void* const* d_in, const int* in_sizes, int n_in,
                              void* d_out, int out_size)
{
    const float* x  = (const float*)d_in[0];
    const float* fc = (const float*)d_in[1];
    const float* fs = (const float*)d_in[2];
    const float* wq = (const float*)d_in[3];
    const float* wk = (const float*)d_in[4];
    const float* wv = (const float*)d_in[5];
    const float* wo = (const float*)d_in[6];

    float* out    = (float*)d_out;
    float* keys   = out + OUT_ELEMS;
    float* values = keys + OUT_ELEMS;

    float *qptr, *kptr, *vptr, *optr;
    cudaGetSymbolAddress((void**)&qptr, g_Q);
    cudaGetSymbolAddress((void**)&kptr, g_K);
    cudaGetSymbolAddress((void**)&vptr, g_V);
    cudaGetSymbolAddress((void**)&optr, g_O);

    cudaFuncSetAttribute(mma_gemm_nt,
                         cudaFuncAttributeMaxDynamicSharedMemorySize, GEMM_SMEM);
    cudaFuncSetAttribute(flash_attn_mma,
                         cudaFuncAttributeMaxDynamicSharedMemorySize, ATTN_SMEM);

    dim3 blk(256);
    dim3 gq(BDIM / 128, MROWS / 128);   // (16, 32)
    dim3 gkv(KVDIM / 128, MROWS / 128); // (4, 32)

    mma_gemm_nt<<<gq,  blk, GEMM_SMEM>>>(x, wq, qptr, MROWS, BDIM,  BDIM);
    mma_gemm_nt<<<gkv, blk, GEMM_SMEM>>>(x, wk, kptr, MROWS, KVDIM, BDIM);
    mma_gemm_nt<<<gkv, blk, GEMM_SMEM>>>(x, wv, vptr, MROWS, KVDIM, BDIM);

    rope_q_kernel<<<MROWS * 1024 / 256, blk>>>(fc, fs);
    rope_k_keys_kernel<<<MROWS * 256 / 256, blk>>>(fc, fs, keys);
    values_copy_kernel<<<MROWS * 128 / 256, blk>>>(values);

    dim3 ga(LSEQ / 64, NB * NH);        // (32, 32)
    flash_attn_mma<<<ga, blk, ATTN_SMEM>>>();

    mma_gemm_nt<<<gq, blk, GEMM_SMEM>>>(optr, wo, out, MROWS, BDIM, BDIM);
}

// round 7
// speedup vs baseline: 3.8501x; 1.2739x over previous
#include <cuda_runtime.h>
#include <cuda_fp16.h>
#include <math.h>
#include <stdint.h>

#define BDIM 2048
#define LSEQ 2048
#define NB   2
#define NH   16
#define NKV  4
#define HDIM 128
#define MROWS (NB*LSEQ)     // 4096
#define KVDIM (NKV*HDIM)    // 512
#define OUT_ELEMS (MROWS*BDIM)

// Scratch (device globals: no allocation allowed in kernel_launch)
__device__ __align__(16) float g_Q[MROWS*BDIM];
__device__ __align__(16) float g_K[MROWS*KVDIM];
__device__ __align__(16) float g_V[MROWS*KVDIM];
__device__ __align__(16) float g_O[MROWS*BDIM];

// ---------------------------------------------------------------------------
// helpers
// ---------------------------------------------------------------------------
__device__ __forceinline__ uint32_t h2u(half2 h) { return *(uint32_t*)&h; }

#define MMA_F16(d, a0, a1, a2, a3, b0, b1)                                    \
    asm volatile("mma.sync.aligned.m16n8k16.row.col.f32.f16.f16.f32 "         \
                 "{%0,%1,%2,%3}, {%4,%5,%6,%7}, {%8,%9}, {%0,%1,%2,%3};"      \
                 : "+f"(d[0]), "+f"(d[1]), "+f"(d[2]), "+f"(d[3])             \
                 : "r"(a0), "r"(a1), "r"(a2), "r"(a3), "r"(b0), "r"(b1))

// ---------------------------------------------------------------------------
// NT HGEMM: C[M,N] = A[M,Kd] * W[N,Kd]^T (row-major fp32 in/out, fp16 mma)
// 128x128 tile, BK=32, 256 threads (8 warps, 64x32 warp tile), double buffer.
// ---------------------------------------------------------------------------
#define PADKH 40      // halfs per row in smem (80B stride)

__global__ __launch_bounds__(256) void hgemm_nt(
    const float* __restrict__ A, const float* __restrict__ W,
    float* __restrict__ C, int N, int Kd)
{
    __shared__ __align__(16) half As[2][128 * PADKH];
    __shared__ __align__(16) half Ws[2][128 * PADKH];

    const int tid  = threadIdx.x;
    const int lane = tid & 31;
    const int wid  = tid >> 5;
    const int g    = lane >> 2;
    const int t    = lane & 3;
    const int wm   = wid & 1;      // 64-row block
    const int wn   = wid >> 1;     // 32-col block
    const int m0   = blockIdx.y << 7;
    const int n0   = blockIdx.x << 7;

    const int lrow = tid >> 3;          // 0..31
    const int lcol = (tid & 7) << 2;    // 0,4,...,28

    float acc[4][4][4];
#pragma unroll
    for (int i = 0; i < 4; i++)
#pragma unroll
        for (int j = 0; j < 4; j++)
#pragma unroll
            for (int r = 0; r < 4; r++) acc[i][j][r] = 0.f;

    const float* Ag = A + (size_t)(m0 + lrow) * Kd + lcol;
    const float* Wg = W + (size_t)(n0 + lrow) * Kd + lcol;

    float4 ra[4], rw[4];
#pragma unroll
    for (int i = 0; i < 4; i++) {
        ra[i] = *(const float4*)(Ag + (size_t)(i * 32) * Kd);
        rw[i] = *(const float4*)(Wg + (size_t)(i * 32) * Kd);
    }

    int p = 0;
    {
#pragma unroll
        for (int i = 0; i < 4; i++) {
            uint2 ua, uw;
            ua.x = h2u(__floats2half2_rn(ra[i].x, ra[i].y));
            ua.y = h2u(__floats2half2_rn(ra[i].z, ra[i].w));
            uw.x = h2u(__floats2half2_rn(rw[i].x, rw[i].y));
            uw.y = h2u(__floats2half2_rn(rw[i].z, rw[i].w));
            *(uint2*)&As[0][(lrow + i * 32) * PADKH + lcol] = ua;
            *(uint2*)&Ws[0][(lrow + i * 32) * PADKH + lcol] = uw;
        }
    }
    __syncthreads();

    for (int k0 = 32; k0 <= Kd; k0 += 32) {
        const bool more = (k0 < Kd);
        if (more) {
#pragma unroll
            for (int i = 0; i < 4; i++) {
                ra[i] = *(const float4*)(Ag + (size_t)(i * 32) * Kd + k0);
                rw[i] = *(const float4*)(Wg + (size_t)(i * 32) * Kd + k0);
            }
        }
        // compute on buffer p
        {
            const half* Ab = As[p];
            const half* Wb = Ws[p];
#pragma unroll
            for (int kk = 0; kk < 32; kk += 16) {
                uint32_t af[4][4], bf[4][2];
#pragma unroll
                for (int i = 0; i < 4; i++) {
                    int row = wm * 64 + i * 16 + g;
                    int base = row * PADKH + kk + 2 * t;
                    af[i][0] = *(const uint32_t*)&Ab[base];
                    af[i][1] = *(const uint32_t*)&Ab[base + 8 * PADKH];
                    af[i][2] = *(const uint32_t*)&Ab[base + 8];
                    af[i][3] = *(const uint32_t*)&Ab[base + 8 * PADKH + 8];
                }
#pragma unroll
                for (int j = 0; j < 4; j++) {
                    int brow = wn * 32 + j * 8 + g;
                    int base = brow * PADKH + kk + 2 * t;
                    bf[j][0] = *(const uint32_t*)&Wb[base];
                    bf[j][1] = *(const uint32_t*)&Wb[base + 8];
                }
#pragma unroll
                for (int i = 0; i < 4; i++)
#pragma unroll
                    for (int j = 0; j < 4; j++)
                        MMA_F16(acc[i][j], af[i][0], af[i][1], af[i][2], af[i][3],
                                bf[j][0], bf[j][1]);
            }
        }
        if (more) {
            int q = 1 - p;
#pragma unroll
            for (int i = 0; i < 4; i++) {
                uint2 ua, uw;
                ua.x = h2u(__floats2half2_rn(ra[i].x, ra[i].y));
                ua.y = h2u(__floats2half2_rn(ra[i].z, ra[i].w));
                uw.x = h2u(__floats2half2_rn(rw[i].x, rw[i].y));
                uw.y = h2u(__floats2half2_rn(rw[i].z, rw[i].w));
                *(uint2*)&As[q][(lrow + i * 32) * PADKH + lcol] = ua;
                *(uint2*)&Ws[q][(lrow + i * 32) * PADKH + lcol] = uw;
            }
            __syncthreads();
            p = q;
        }
    }

    // epilogue
#pragma unroll
    for (int i = 0; i < 4; i++) {
        int row = m0 + wm * 64 + i * 16 + g;
#pragma unroll
        for (int j = 0; j < 4; j++) {
            int col = n0 + wn * 32 + j * 8 + 2 * t;
            *(float2*)&C[(size_t)row * N + col] = make_float2(acc[i][j][0], acc[i][j][1]);
            *(float2*)&C[(size_t)(row + 8) * N + col] = make_float2(acc[i][j][2], acc[i][j][3]);
        }
    }
}

// ---------------------------------------------------------------------------
// RoPE on Q (in place).
// ---------------------------------------------------------------------------
__global__ void rope_q_kernel(const float* __restrict__ fc, const float* __restrict__ fs)
{
    int idx = blockIdx.x * blockDim.x + threadIdx.x;
    int bl = idx >> 10;
    int p  = idx & 1023;
    int h  = p >> 6;
    int dp = p & 63;
    int l  = bl & (LSEQ - 1);
    float c = fc[l * 64 + dp];
    float s = fs[l * 64 + dp];
    float2* q = (float2*)&g_Q[(size_t)bl * BDIM + h * HDIM + dp * 2];
    float2 v = *q;
    float2 r;
    r.x = v.x * c - v.y * s;
    r.y = v.x * s + v.y * c;
    *q = r;
}

// ---------------------------------------------------------------------------
// RoPE on K (in place) + keys output [B, NH, L, HD] (4-way replication)
// ---------------------------------------------------------------------------
__global__ void rope_k_keys_kernel(const float* __restrict__ fc, const float* __restrict__ fs,
                                   float* __restrict__ keys)
{
    int idx = blockIdx.x * blockDim.x + threadIdx.x;
    int bl  = idx >> 8;
    int p   = idx & 255;
    int kvh = p >> 6;
    int dp  = p & 63;
    int b   = bl >> 11;
    int l   = bl & (LSEQ - 1);
    float c = fc[l * 64 + dp];
    float s = fs[l * 64 + dp];
    float2* kp = (float2*)&g_K[(size_t)bl * KVDIM + kvh * HDIM + dp * 2];
    float2 v = *kp;
    float2 r;
    r.x = v.x * c - v.y * s;
    r.y = v.x * s + v.y * c;
    *kp = r;
#pragma unroll
    for (int rep = 0; rep < 4; rep++) {
        int h = kvh * 4 + rep;
        *(float2*)&keys[(((size_t)(b * NH + h)) * LSEQ + l) * HDIM + dp * 2] = r;
    }
}

// ---------------------------------------------------------------------------
// values output: replicate V 4x into [B, NH, L, HD]
// ---------------------------------------------------------------------------
__global__ void values_copy_kernel(float* __restrict__ values)
{
    int idx = blockIdx.x * blockDim.x + threadIdx.x;
    int bl  = idx >> 7;
    int p   = idx & 127;
    int kvh = p >> 5;
    int c4  = p & 31;
    int b   = bl >> 11;
    int l   = bl & (LSEQ - 1);
    float4 v = *(const float4*)&g_V[(size_t)bl * KVDIM + p * 4];
#pragma unroll
    for (int rep = 0; rep < 4; rep++) {
        int h = kvh * 4 + rep;
        *(float4*)&values[(((size_t)(b * NH + h)) * LSEQ + l) * HDIM + c4 * 4] = v;
    }
}

// ---------------------------------------------------------------------------
// Flash attention, fp16 mma (fp32 softmax + accumulators).
// BR=BC=64, HD=128, 256 threads (8 warps): wm=wid&3 (16 rows), wn=wid>>2.
// smem: Qh[64][136]h, Kh[64][136]h (reused as interleaved V), Ss[64][76]f,
//       Ph[64][72]h, row stats (768B; 1024 reserved).
// ---------------------------------------------------------------------------
#define PADQH 136
#define PADS  76
#define PADPH 72
#define VPAD  264      // halfs per k-pair row of interleaved V
#define ATTN_SMEM (64*PADQH*2 + 64*PADQH*2 + 64*PADS*4 + 64*PADPH*2 + 1024)

__global__ __launch_bounds__(256) void flash_attn_h()
{
    extern __shared__ char smraw[];
    half*  Qh     = (half*)smraw;
    half*  Kh     = Qh + 64 * PADQH;          // reused as Vs2 (32*VPAD halfs)
    float* Ss     = (float*)(Kh + 64 * PADQH);
    half*  Ph     = (half*)(Ss + 64 * PADS);
    float* row_m  = (float*)(Ph + 64 * PADPH);
    float* row_l  = row_m + 64;
    float* row_al = row_l + 64;

    const int tid  = threadIdx.x;
    const int lane = tid & 31;
    const int wid  = tid >> 5;
    const int g    = lane >> 2;
    const int t    = lane & 3;
    const int wm   = wid & 3;
    const int wn   = wid >> 2;

    const int qt = blockIdx.x;
    const int bh = blockIdx.y;
    const int b  = bh >> 4;
    const int h  = bh & 15;
    const int kv = h >> 2;
    const int q0 = qt * 64;

    const size_t qbase = ((size_t)(b * LSEQ + q0)) * BDIM + h * HDIM;
    const size_t kbase = ((size_t)(b * LSEQ)) * KVDIM + kv * HDIM;

    // Load Q tile (64x128 fp32 -> half)
#pragma unroll
    for (int pp = 0; pp < 8; pp++) {
        int id = tid + pp * 256;
        int r  = id >> 5, c4 = (id & 31) << 2;
        float4 v = *(const float4*)&g_Q[qbase + (size_t)r * BDIM + c4];
        uint2 u;
        u.x = h2u(__floats2half2_rn(v.x, v.y));
        u.y = h2u(__floats2half2_rn(v.z, v.w));
        *(uint2*)&Qh[r * PADQH + c4] = u;
    }
    if (tid < 64) { row_m[tid] = -1e30f; row_l[tid] = 0.f; }

    const int sr = tid >> 2;
    const int sq = tid & 3;

    float o[8][4];
#pragma unroll
    for (int j = 0; j < 8; j++)
#pragma unroll
        for (int r = 0; r < 4; r++) o[j][r] = 0.f;

    const float scale = 0.08838834764831845f;
    const int ntiles = qt + 1;

    for (int jt = 0; jt < ntiles; jt++) {
        __syncthreads();   // prev iter PV reads of Ph/Vs2 done

        // Load K tile (64x128 -> half)
#pragma unroll
        for (int pp = 0; pp < 8; pp++) {
            int id = tid + pp * 256;
            int r  = id >> 5, c4 = (id & 31) << 2;
            float4 v = *(const float4*)&g_K[kbase + (size_t)(jt * 64 + r) * KVDIM + c4];
            uint2 u;
            u.x = h2u(__floats2half2_rn(v.x, v.y));
            u.y = h2u(__floats2half2_rn(v.z, v.w));
            *(uint2*)&Kh[r * PADQH + c4] = u;
        }
        __syncthreads();

        // S = Q K^T : per warp m16 x 4 n8 tiles, k=128 (8 steps of k16)
        float sacc[4][4];
#pragma unroll
        for (int j = 0; j < 4; j++)
#pragma unroll
            for (int r = 0; r < 4; r++) sacc[j][r] = 0.f;

#pragma unroll
        for (int kk = 0; kk < 128; kk += 16) {
            int row = wm * 16 + g;
            int ab = row * PADQH + kk + 2 * t;
            uint32_t a0 = *(const uint32_t*)&Qh[ab];
            uint32_t a1 = *(const uint32_t*)&Qh[ab + 8 * PADQH];
            uint32_t a2 = *(const uint32_t*)&Qh[ab + 8];
            uint32_t a3 = *(const uint32_t*)&Qh[ab + 8 * PADQH + 8];
#pragma unroll
            for (int j = 0; j < 4; j++) {
                int bb = (wn * 32 + j * 8 + g) * PADQH + kk + 2 * t;
                uint32_t b0 = *(const uint32_t*)&Kh[bb];
                uint32_t b1 = *(const uint32_t*)&Kh[bb + 8];
                MMA_F16(sacc[j], a0, a1, a2, a3, b0, b1);
            }
        }

        // scale + causal mask (diag tile) + store S (fp32) for softmax
        const bool diag = (jt == qt);
#pragma unroll
        for (int j = 0; j < 4; j++) {
            int r0 = wm * 16 + g;
            int c0 = wn * 32 + j * 8 + 2 * t;
            float s0 = sacc[j][0] * scale;
            float s1 = sacc[j][1] * scale;
            float s2 = sacc[j][2] * scale;
            float s3 = sacc[j][3] * scale;
            if (diag) {
                if (c0     > r0)     s0 = -1e30f;
                if (c0 + 1 > r0)     s1 = -1e30f;
                if (c0     > r0 + 8) s2 = -1e30f;
                if (c0 + 1 > r0 + 8) s3 = -1e30f;
            }
            *(float2*)&Ss[r0 * PADS + c0]       = make_float2(s0, s1);
            *(float2*)&Ss[(r0 + 8) * PADS + c0] = make_float2(s2, s3);
        }
        __syncthreads();

        // online softmax (4 threads per row); P stored as half into Ph
        {
            float4 sv[4];
            float pmax = -1e30f;
#pragma unroll
            for (int tt = 0; tt < 4; tt++) {
                sv[tt] = *(const float4*)&Ss[sr * PADS + sq * 16 + tt * 4];
                pmax = fmaxf(pmax, fmaxf(fmaxf(sv[tt].x, sv[tt].y), fmaxf(sv[tt].z, sv[tt].w)));
            }
            pmax = fmaxf(pmax, __shfl_xor_sync(0xffffffffu, pmax, 1));
            pmax = fmaxf(pmax, __shfl_xor_sync(0xffffffffu, pmax, 2));
            float mold = row_m[sr];
            float mnew = fmaxf(mold, pmax);
            float alpha = __expf(mold - mnew);
            float lsum = 0.f;
#pragma unroll
            for (int tt = 0; tt < 4; tt++) {
                sv[tt].x = __expf(sv[tt].x - mnew);
                sv[tt].y = __expf(sv[tt].y - mnew);
                sv[tt].z = __expf(sv[tt].z - mnew);
                sv[tt].w = __expf(sv[tt].w - mnew);
                lsum += sv[tt].x + sv[tt].y + sv[tt].z + sv[tt].w;
                uint2 u;
                u.x = h2u(__floats2half2_rn(sv[tt].x, sv[tt].y));
                u.y = h2u(__floats2half2_rn(sv[tt].z, sv[tt].w));
                *(uint2*)&Ph[sr * PADPH + sq * 16 + tt * 4] = u;
            }
            lsum += __shfl_xor_sync(0xffffffffu, lsum, 1);
            lsum += __shfl_xor_sync(0xffffffffu, lsum, 2);
            if (sq == 0) {
                row_l[sr]  = row_l[sr] * alpha + lsum;
                row_m[sr]  = mnew;
                row_al[sr] = alpha;
            }
        }

        // Load V tile into Kh buffer, k-pair interleaved:
        // Vs2[(r>>1)*VPAD + c*2 + (r&1)] = half(V[r][c])
        {
            half* Vs2 = Kh;
#pragma unroll
            for (int pp = 0; pp < 8; pp++) {
                int id = tid + pp * 256;
                int r  = id >> 5, c4 = (id & 31) << 2;
                float4 v = *(const float4*)&g_V[kbase + (size_t)(jt * 64 + r) * KVDIM + c4];
                int base = (r >> 1) * VPAD + c4 * 2 + (r & 1);
                Vs2[base]     = __float2half_rn(v.x);
                Vs2[base + 2] = __float2half_rn(v.y);
                Vs2[base + 4] = __float2half_rn(v.z);
                Vs2[base + 6] = __float2half_rn(v.w);
            }
        }
        __syncthreads();

        // rescale O by alpha
        float al0 = row_al[wm * 16 + g];
        float al1 = row_al[wm * 16 + g + 8];
#pragma unroll
        for (int j = 0; j < 8; j++) {
            o[j][0] *= al0; o[j][1] *= al0;
            o[j][2] *= al1; o[j][3] *= al1;
        }

        // O += P V : per warp m16 x 8 n8 tiles, k=64 (4 steps of k16)
        {
            const half* Vs2 = Kh;
#pragma unroll
            for (int kk = 0; kk < 64; kk += 16) {
                int row = wm * 16 + g;
                int ab = row * PADPH + kk + 2 * t;
                uint32_t a0 = *(const uint32_t*)&Ph[ab];
                uint32_t a1 = *(const uint32_t*)&Ph[ab + 8 * PADPH];
                uint32_t a2 = *(const uint32_t*)&Ph[ab + 8];
                uint32_t a3 = *(const uint32_t*)&Ph[ab + 8 * PADPH + 8];
#pragma unroll
                for (int j = 0; j < 8; j++) {
                    int n = wn * 64 + j * 8 + g;
                    uint32_t b0 = *(const uint32_t*)&Vs2[(kk / 2 + t) * VPAD + n * 2];
                    uint32_t b1 = *(const uint32_t*)&Vs2[(kk / 2 + 4 + t) * VPAD + n * 2];
                    MMA_F16(o[j], a0, a1, a2, a3, b0, b1);
                }
            }
        }
    }

    // final normalize + store O ([B, L, H*HD] layout, fp32)
    const size_t obase = ((size_t)(b * LSEQ + q0)) * BDIM + h * HDIM;
    float linv0 = 1.f / row_l[wm * 16 + g];
    float linv1 = 1.f / row_l[wm * 16 + g + 8];
    int r0 = wm * 16 + g;
#pragma unroll
    for (int j = 0; j < 8; j++) {
        int col = wn * 64 + j * 8 + 2 * t;
        *(float2*)&g_O[obase + (size_t)r0 * BDIM + col] =
            make_float2(o[j][0] * linv0, o[j][1] * linv0);
        *(float2*)&g_O[obase + (size_t)(r0 + 8) * BDIM + col] =
            make_float2(o[j][2] * linv1, o[j][3] * linv1);
    }
}

// ---------------------------------------------------------------------------
extern "C" void kernel_launch(void* const* d_in, const int* in_sizes, int n_in,
                              void* d_out, int out_size)
{
    const float* x  = (const float*)d_in[0];
    const float* fc = (const float*)d_in[1];
    const float* fs = (const float*)d_in[2];
    const float* wq = (const float*)d_in[3];
    const float* wk = (const float*)d_in[4];
    const float* wv = (const float*)d_in[5];
    const float* wo = (const float*)d_in[6];

    float* out    = (float*)d_out;
    float* keys   = out + OUT_ELEMS;
    float* values = keys + OUT_ELEMS;

    float *qptr, *kptr, *vptr, *optr;
    cudaGetSymbolAddress((void**)&qptr, g_Q);
    cudaGetSymbolAddress((void**)&kptr, g_K);
    cudaGetSymbolAddress((void**)&vptr, g_V);
    cudaGetSymbolAddress((void**)&optr, g_O);

    cudaFuncSetAttribute(flash_attn_h,
                         cudaFuncAttributeMaxDynamicSharedMemorySize, ATTN_SMEM);

    dim3 blk(256);
    dim3 gq(BDIM / 128, MROWS / 128);   // (16, 32)
    dim3 gkv(KVDIM / 128, MROWS / 128); // (4, 32)

    hgemm_nt<<<gq,  blk>>>(x, wq, qptr, BDIM,  BDIM);
    hgemm_nt<<<gkv, blk>>>(x, wk, kptr, KVDIM, BDIM);
    hgemm_nt<<<gkv, blk>>>(x, wv, vptr, KVDIM, BDIM);

    rope_q_kernel<<<MROWS * 1024 / 256, blk>>>(fc, fs);
    rope_k_keys_kernel<<<MROWS * 256 / 256, blk>>>(fc, fs, keys);
    values_copy_kernel<<<MROWS * 128 / 256, blk>>>(values);

    dim3 ga(LSEQ / 64, NB * NH);        // (32, 32)
    flash_attn_h<<<ga, blk, ATTN_SMEM>>>();

    hgemm_nt<<<gq, blk>>>(optr, wo, out, BDIM, BDIM);
}